// round 4
// baseline (speedup 1.0000x reference)
#include <cuda_runtime.h>

#define B_    4096
#define N0_   2048
#define N1_   1000
#define N2_   500
#define N3_   100
#define C_    100
#define NDIM_ 3
#define NCLS_ 12

// -------- scratch (device globals: no allocation allowed) --------
__device__ float g_h1[(size_t)B_ * N1_];   // 16.4 MB
__device__ float g_h2[(size_t)B_ * N2_];   // 8.2 MB
__device__ int   g_idx[B_];
__device__ int   g_counts[C_];
__device__ int   g_offsets[C_];
__device__ int   g_cursor[C_];
__device__ int   g_order[B_];

// ============================================================================
// Tiled fp32 SGEMM, double-buffered smem pipeline:
//   C[M,N] = op(A[M,K] @ B[K,N] + bias[N]), op = relu or identity
// BMt x 128 tile, BK=8, NT=BMt*2 threads, 8x8 microtile
// (16 x NT/16 thread grid covers 128 x BMt outputs), float4 everywhere,
// ONE __syncthreads per K-tile.
// ============================================================================
#define BN  128
#define BKs 8
#define BNP 132

template <bool RELU, int BMt>
__global__ __launch_bounds__(BMt * 2)
void sgemm_bias(const float* __restrict__ A, const float* __restrict__ Bm,
                const float* __restrict__ bias, float* __restrict__ Cm,
                int M, int N, int K)
{
    constexpr int NT  = BMt * 2;              // threads (256 / 128)
    constexpr int MI  = (BMt * 16) / NT;      // rows per thread = 8 (both cases)
    constexpr int BMP = BMt + 4;
    constexpr int BV  = (BKs * BN / 4) / NT;  // B-tile float4s per thread (1 / 2)
    static_assert(MI * (NT / 16) == BMt, "row coverage must equal BMt");
    static_assert(BV * NT * 4 == BKs * BN, "B tile must divide evenly");

    __shared__ float As[2][BKs][BMP];   // transposed: As[buf][k][m]
    __shared__ float Bs[2][BKs][BNP];

    const int tid = threadIdx.x;
    const int m0  = blockIdx.y * BMt;
    const int n0  = blockIdx.x * BN;
    const int tx  = tid & 15;                   // 16 col-thread groups
    const int ty  = tid >> 4;                   // NT/16 row-thread groups
    // A tile: BMt x 8 = NT float4s -> exactly one per thread
    const int arow = tid / (BKs / 4);           // 0..BMt-1
    const int acol = (tid % (BKs / 4)) << 2;    // 0 or 4

    float acc[MI][8];
#pragma unroll
    for (int i = 0; i < MI; i++)
#pragma unroll
        for (int j = 0; j < 8; j++) acc[i][j] = 0.f;

    const int nTiles = (K + BKs - 1) / BKs;

    // ---- guarded global loaders (into registers) ----
    auto loadA = [&](int k0) -> float4 {
        float4 v = make_float4(0.f, 0.f, 0.f, 0.f);
        int gm = m0 + arow, gk = k0 + acol;
        if (gm < M) {
            if (gk + 3 < K) v = *reinterpret_cast<const float4*>(A + (size_t)gm * K + gk);
            else {
                if (gk + 0 < K) v.x = A[(size_t)gm * K + gk + 0];
                if (gk + 1 < K) v.y = A[(size_t)gm * K + gk + 1];
                if (gk + 2 < K) v.z = A[(size_t)gm * K + gk + 2];
            }
        }
        return v;
    };
    auto loadB = [&](int k0, float4* out) {
#pragma unroll
        for (int v = 0; v < BV; v++) {
            int idx  = tid + v * NT;            // 0..(BKs*BN/4)-1
            int brow = (idx * 4) / BN;
            int bcol = (idx * 4) % BN;
            float4 r = make_float4(0.f, 0.f, 0.f, 0.f);
            int gkb = k0 + brow, gn = n0 + bcol;
            if (gkb < K) {
                if (gn + 3 < N) r = *reinterpret_cast<const float4*>(Bm + (size_t)gkb * N + gn);
                else {
                    if (gn + 0 < N) r.x = Bm[(size_t)gkb * N + gn + 0];
                    if (gn + 1 < N) r.y = Bm[(size_t)gkb * N + gn + 1];
                    if (gn + 2 < N) r.z = Bm[(size_t)gkb * N + gn + 2];
                }
            }
            out[v] = r;
        }
    };
    auto stage = [&](int buf, float4 av, const float4* bv) {
        As[buf][acol + 0][arow] = av.x;
        As[buf][acol + 1][arow] = av.y;
        As[buf][acol + 2][arow] = av.z;
        As[buf][acol + 3][arow] = av.w;
#pragma unroll
        for (int v = 0; v < BV; v++) {
            int idx  = tid + v * NT;
            int brow = (idx * 4) / BN;
            int bcol = (idx * 4) % BN;
            *reinterpret_cast<float4*>(&Bs[buf][brow][bcol]) = bv[v];
        }
    };

    // prologue: stage tile 0
    {
        float4 av = loadA(0), bv[BV];
        loadB(0, bv);
        stage(0, av, bv);
    }
    __syncthreads();

    int buf = 0;
    for (int t = 0; t < nTiles; t++) {
        // prefetch next tile into registers (overlaps with FFMA below)
        float4 avn, bvn[BV];
        const bool more = (t + 1 < nTiles);
        if (more) { avn = loadA((t + 1) * BKs); loadB((t + 1) * BKs, bvn); }

        // compute on current buffer
#pragma unroll
        for (int k = 0; k < BKs; k++) {
            float a[MI], b[8];
#pragma unroll
            for (int q = 0; q < MI; q += 4)
                *reinterpret_cast<float4*>(&a[q]) =
                    *reinterpret_cast<float4*>(&As[buf][k][ty * MI + q]);
            *reinterpret_cast<float4*>(&b[0]) = *reinterpret_cast<float4*>(&Bs[buf][k][tx * 8 + 0]);
            *reinterpret_cast<float4*>(&b[4]) = *reinterpret_cast<float4*>(&Bs[buf][k][tx * 8 + 4]);
#pragma unroll
            for (int i = 0; i < MI; i++)
#pragma unroll
                for (int j = 0; j < 8; j++) acc[i][j] += a[i] * b[j];
        }

        // stage next tile into the other buffer, single barrier
        if (more) stage(buf ^ 1, avn, bvn);
        __syncthreads();
        buf ^= 1;
    }

    // ---- epilogue: bias (+relu), guarded store ----
#pragma unroll
    for (int i = 0; i < MI; i++) {
        int row = m0 + ty * MI + i;
        if (row >= M) continue;
#pragma unroll
        for (int j = 0; j < 8; j++) {
            int col = n0 + tx * 8 + j;
            if (col >= N) continue;
            float v = acc[i][j] + bias[col];
            if (RELU) v = fmaxf(v, 0.f);
            Cm[(size_t)row * N + col] = v;
        }
    }
}

// ============================================================================
// Category head: y0 = x @ Wcat + bcat   (N=12, one warp per row)
// ============================================================================
__global__ void cat_head_kernel(const float* __restrict__ x,
                                const float* __restrict__ Wcat,
                                const float* __restrict__ bcat,
                                float* __restrict__ y0)
{
    int gt   = blockIdx.x * blockDim.x + threadIdx.x;
    int row  = gt >> 5;
    int lane = gt & 31;
    if (row >= B_) return;

    const float* xr = x + (size_t)row * N0_;
    float acc[NCLS_];
#pragma unroll
    for (int c = 0; c < NCLS_; c++) acc[c] = 0.f;

    for (int k = lane; k < N0_; k += 32) {
        float xv = xr[k];
        const float* wr = Wcat + (size_t)k * NCLS_;
#pragma unroll
        for (int c = 0; c < NCLS_; c++) acc[c] += xv * wr[c];
    }
#pragma unroll
    for (int c = 0; c < NCLS_; c++) {
        float v = acc[c];
#pragma unroll
        for (int off = 16; off; off >>= 1) v += __shfl_xor_sync(0xffffffffu, v, off);
        if (lane == 0) y0[(size_t)row * NCLS_ + c] = v + bcat[c];
    }
}

// ============================================================================
// argmax(y1, axis=1) per row (first-max semantics) + bucket counts
// ============================================================================
__global__ void zero_counts_kernel()
{
    if (threadIdx.x < C_) g_counts[threadIdx.x] = 0;
}

__global__ void argmax_count_kernel(const float* __restrict__ y1)
{
    int gt   = blockIdx.x * blockDim.x + threadIdx.x;
    int row  = gt >> 5;
    int lane = gt & 31;
    if (row >= B_) return;

    const float* r = y1 + (size_t)row * C_;
    float best = -3.4e38f;
    int   bi   = 0;
    for (int c = lane; c < C_; c += 32) {
        float v = r[c];
        if (v > best) { best = v; bi = c; }   // ascending scan -> first max kept
    }
#pragma unroll
    for (int off = 16; off; off >>= 1) {
        float ov = __shfl_xor_sync(0xffffffffu, best, off);
        int   oi = __shfl_xor_sync(0xffffffffu, bi, off);
        if (ov > best || (ov == best && oi < bi)) { best = ov; bi = oi; }
    }
    if (lane == 0) {
        g_idx[row] = bi;
        atomicAdd(&g_counts[bi], 1);
    }
}

__global__ void prefix_kernel()
{
    if (threadIdx.x == 0) {
        int s = 0;
        for (int c = 0; c < C_; c++) {
            g_offsets[c] = s;
            g_cursor[c]  = s;
            s += g_counts[c];
        }
    }
}

__global__ void scatter_kernel()
{
    int b = blockIdx.x * blockDim.x + threadIdx.x;
    if (b >= B_) return;
    int e = g_idx[b];
    int p = atomicAdd(&g_cursor[e], 1);
    g_order[p] = b;   // within-bucket order nondeterministic, output invariant
}

// ============================================================================
// Selected-expert MLP: for each bucket e, tiles of 32 samples:
//   he = relu(x_tile @ We1[e] + be1[e])   [32 x 100]
//   y2 = he @ We2[e] + be2[e]             [32 x 3]
// Only the chosen expert per sample is computed (100x FLOP reduction vs ref).
// ============================================================================
#define EM  32
#define EBK 16

__global__ __launch_bounds__(256)
void expert_kernel(const float* __restrict__ x,
                   const float* __restrict__ We1, const float* __restrict__ be1,
                   const float* __restrict__ We2, const float* __restrict__ be2,
                   float* __restrict__ y2)
{
    const int e   = blockIdx.x;
    const int cnt = g_counts[e];
    const int t0  = blockIdx.y * EM;
    if (t0 >= cnt) return;
    const int start = g_offsets[e];
    const int rows  = min(EM, cnt - t0);

    __shared__ int   rid[EM];
    __shared__ float xs[EM][EBK];       // 2 KB
    __shared__ float Ws[EBK][128];      // 8 KB (cols 100..127 zero-padded)
    __shared__ float hs[EM][104];       // 13.3 KB
    __shared__ float w2s[N3_ * NDIM_];  // 1.2 KB
    __shared__ float be1s[128];
    __shared__ float be2s[4];

    const int tid = threadIdx.x;
    if (tid < EM) rid[tid] = g_order[start + t0 + min(tid, rows - 1)];
    for (int i = tid; i < N3_ * NDIM_; i += 256) w2s[i] = We2[(size_t)e * N3_ * NDIM_ + i];
    if (tid < NDIM_) be2s[tid] = be2[(size_t)e * NDIM_ + tid];
    if (tid < 128)   be1s[tid] = (tid < N3_) ? be1[(size_t)e * N3_ + tid] : 0.f;
    __syncthreads();

    const int tx = tid & 31;   // col group: cols tx*4 .. tx*4+3
    const int ty = tid >> 5;   // rows ty, ty+8, ty+16, ty+24
    float acc[4][4];
#pragma unroll
    for (int i = 0; i < 4; i++)
#pragma unroll
        for (int j = 0; j < 4; j++) acc[i][j] = 0.f;

    for (int k0 = 0; k0 < N0_; k0 += EBK) {
        if (tid < 128) {
            int r  = tid >> 2;
            int kq = (tid & 3) << 2;
            float4 v = *reinterpret_cast<const float4*>(x + (size_t)rid[r] * N0_ + k0 + kq);
            *reinterpret_cast<float4*>(&xs[r][kq]) = v;
        }
        const float* wbase = We1 + ((size_t)e * N0_ + k0) * N3_;
        for (int i = tid; i < EBK * 128; i += 256) {
            int k = i >> 7, c = i & 127;
            Ws[k][c] = (c < N3_) ? wbase[(size_t)k * N3_ + c] : 0.f;
        }
        __syncthreads();

#pragma unroll
        for (int k = 0; k < EBK; k++) {
            float a0 = xs[ty +  0][k];
            float a1 = xs[ty +  8][k];
            float a2 = xs[ty + 16][k];
            float a3 = xs[ty + 24][k];
            float4 bv = *reinterpret_cast<float4*>(&Ws[k][tx * 4]);
            acc[0][0] += a0 * bv.x; acc[0][1] += a0 * bv.y; acc[0][2] += a0 * bv.z; acc[0][3] += a0 * bv.w;
            acc[1][0] += a1 * bv.x; acc[1][1] += a1 * bv.y; acc[1][2] += a1 * bv.z; acc[1][3] += a1 * bv.w;
            acc[2][0] += a2 * bv.x; acc[2][1] += a2 * bv.y; acc[2][2] += a2 * bv.z; acc[2][3] += a2 * bv.w;
            acc[3][0] += a3 * bv.x; acc[3][1] += a3 * bv.y; acc[3][2] += a3 * bv.z; acc[3][3] += a3 * bv.w;
        }
        __syncthreads();
    }

    // he = relu(acc + be1), staged to shared (only valid cols < 100)
    if (tx < 25) {
#pragma unroll
        for (int i = 0; i < 4; i++) {
            int r = ty + 8 * i;
            float4 h;
            h.x = fmaxf(acc[i][0] + be1s[tx * 4 + 0], 0.f);
            h.y = fmaxf(acc[i][1] + be1s[tx * 4 + 1], 0.f);
            h.z = fmaxf(acc[i][2] + be1s[tx * 4 + 2], 0.f);
            h.w = fmaxf(acc[i][3] + be1s[tx * 4 + 3], 0.f);
            *reinterpret_cast<float4*>(&hs[r][tx * 4]) = h;
        }
    }
    __syncthreads();

    // y2 = he @ We2[e] + be2[e]: 96 tasks (32 rows x 3 dims)
    if (tid < EM * NDIM_) {
        int r = tid / NDIM_, d = tid % NDIM_;
        if (r < rows) {
            float s = be2s[d];
#pragma unroll 4
            for (int k = 0; k < N3_; k++) s += hs[r][k] * w2s[k * NDIM_ + d];
            y2[(size_t)rid[r] * NDIM_ + d] = s;
        }
    }
}

// ============================================================================
extern "C" void kernel_launch(void* const* d_in, const int* in_sizes, int n_in,
                              void* d_out, int out_size)
{
    const float* x    = (const float*)d_in[0];
    const float* Wcat = (const float*)d_in[1];
    const float* bcat = (const float*)d_in[2];
    const float* Wb1  = (const float*)d_in[3];
    const float* bb1  = (const float*)d_in[4];
    const float* Wb2  = (const float*)d_in[5];
    const float* bb2  = (const float*)d_in[6];
    const float* Wb3  = (const float*)d_in[7];
    const float* bb3  = (const float*)d_in[8];
    const float* We1  = (const float*)d_in[9];
    const float* be1  = (const float*)d_in[10];
    const float* We2  = (const float*)d_in[11];
    const float* be2  = (const float*)d_in[12];

    float* out = (float*)d_out;
    float* y0  = out;                                   // [B, 12]
    float* y1  = out + (size_t)B_ * NCLS_;              // [B, 100]
    float* y2  = out + (size_t)B_ * (NCLS_ + C_);       // [B, 3]

    float *h1, *h2;
    cudaGetSymbolAddress((void**)&h1, g_h1);
    cudaGetSymbolAddress((void**)&h2, g_h2);

    // bin-head MLP (the argmax driver) + y1 output
    sgemm_bias<true, 128><<<dim3((N1_ + BN - 1) / BN, B_ / 128), 256>>>(x,  Wb1, bb1, h1, B_, N1_, N0_);
    sgemm_bias<true, 128><<<dim3((N2_ + BN - 1) / BN, B_ / 128), 256>>>(h1, Wb2, bb2, h2, B_, N2_, N1_);
    // N=100 -> one 128-wide col tile; BM=64 -> 64 blocks (better SM fill)
    sgemm_bias<false, 64><<<dim3(1, B_ / 64), 128>>>(h2, Wb3, bb3, y1, B_, C_, N2_);

    // category head (independent)
    cat_head_kernel<<<(B_ * 32 + 255) / 256, 256>>>(x, Wcat, bcat, y0);

    // argmax -> bucket samples by chosen expert
    zero_counts_kernel<<<1, 128>>>();
    argmax_count_kernel<<<(B_ * 32 + 255) / 256, 256>>>(y1);
    prefix_kernel<<<1, 32>>>();
    scatter_kernel<<<(B_ + 255) / 256, 256>>>();

    // compute ONLY the selected expert per sample (100x FLOP cut vs reference)
    expert_kernel<<<dim3(C_, (B_ + EM - 1) / EM), 256>>>(x, We1, be1, We2, be2, y2);
}